// round 12
// baseline (speedup 1.0000x reference)
#include <cuda_runtime.h>

#define NCLS 32
#define SOSC 30
#define EOSC 31
#define LOG2E 1.4426950408889634f
#define LN2F  0.6931471805599453f

typedef unsigned long long u64;

__device__ __forceinline__ float ex2f(float x){ float r; asm("ex2.approx.f32 %0, %1;" : "=f"(r) : "f"(x)); return r; }
__device__ __forceinline__ float lg2f_(float x){ float r; asm("lg2.approx.f32 %0, %1;" : "=f"(r) : "f"(x)); return r; }
__device__ __forceinline__ u64 pk2(float lo, float hi){ u64 r; asm("mov.b64 %0, {%1,%2};" : "=l"(r) : "f"(lo), "f"(hi)); return r; }
__device__ __forceinline__ void up2(u64 v, float& lo, float& hi){ asm("mov.b64 {%0,%1}, %2;" : "=f"(lo), "=f"(hi) : "l"(v)); }
__device__ __forceinline__ u64 ffma2(u64 a, u64 b, u64 c){ u64 d; asm("fma.rn.f32x2 %0, %1, %2, %3;" : "=l"(d) : "l"(a), "l"(b), "l"(c)); return d; }
__device__ __forceinline__ u64 fadd2(u64 a, u64 b){ u64 d; asm("add.rn.f32x2 %0, %1, %2;" : "=l"(d) : "l"(a), "l"(b)); return d; }
__device__ __forceinline__ u64 fmul2(u64 a, u64 b){ u64 d; asm("mul.rn.f32x2 %0, %1, %2;" : "=l"(d) : "l"(a), "l"(b)); return d; }

// 64-bit idx-shuffle via two independent 32-bit shfl.idx.
__device__ __forceinline__ u64 shfl64(u64 v, int src){
    float lo, hi; up2(v, lo, hi);
    lo = __shfl_sync(0xffffffffu, lo, src);
    hi = __shfl_sync(0xffffffffu, hi, src);
    return pk2(lo, hi);
}

// Exact power-of-2 rescale factor from a stale probe value d (pure ALU).
__device__ __forceinline__ float po2_rescale(float d, int& eacc){
    unsigned u = __float_as_uint(d);
    int e = (int)(u >> 23) & 0xff;
    if (e == 0 || e >= 254) return 1.0f;
    eacc += (e - 127);
    return __uint_as_float((unsigned)(254 - e) << 23);
}

// Exp-domain CRF forward (R9 layout): 1 warp = 2 batches; 16 lanes/batch;
// lane = (4-class group gc) x (k-half kh); exchange = 16 shfl.32 (minimum),
// partner combine = 4 scalar shfl+add. Path surgery vs R9:
//  - po2 rescale folded into prefetched fe[j] BEFORE the exchange (off-path;
//    exact: r is a power of 2), gated off when mask==0 so state/eC stay sync.
//  - SEL blend (pred ? Pn : P2): rounding-free under any scale mix (required
//    with fe-folding), exact for binary masks, ALU pipe, shorter path.
__global__ __launch_bounds__(32, 8)
void crf_fwd(const float* __restrict__ feats,
             const float* __restrict__ mask,
             const float* __restrict__ trans,
             float* __restrict__ out,
             int seq, int batch)
{
    const int lane = threadIdx.x & 31;
    const int b    = lane >> 4;       // batch slot (0..1)
    const int g    = lane & 15;
    const int gc   = g & 7;           // class group -> classes 4gc..4gc+3
    const int kh   = g >> 3;          // k-half: k in [16*kh, 16*kh+16)
    const int c0   = gc * 4;
    const int k0   = kh * 16;
    const int batch0 = blockIdx.x * 2;
    int bb = batch0 + b;
    const bool real = (bb < batch);
    if (!real) bb = batch - 1;
    // exchange source base: lane holding class quad (4*kh + qi) of this batch
    const int xbase = (lane & 16) | (kh << 2);

    // E2[ci][kp] = (exp T[c0+ci][k0+2kp], exp T[c0+ci][k0+2kp+1])  (32 u64)
    u64 E2[4][8];
#pragma unroll
    for (int ci = 0; ci < 4; ++ci){
        const float* tr = trans + (c0 + ci) * NCLS + k0;
#pragma unroll
        for (int kp = 0; kp < 8; ++kp)
            E2[ci][kp] = pk2(ex2f(tr[2*kp] * LOG2E), ex2f(tr[2*kp+1] * LOG2E));
    }
    u64 ee2[2];
    {
        const float* te = trans + EOSC * NCLS + c0;
        ee2[0] = pk2(ex2f(te[0]*LOG2E), ex2f(te[1]*LOG2E));
        ee2[1] = pk2(ex2f(te[2]*LOG2E), ex2f(te[3]*LOG2E));
    }

    // State: P for this lane's 4 classes (identical across k-partner lanes).
    u64 P2[2];
    P2[0] = pk2((c0+0==SOSC)?1.f:0.f, (c0+1==SOSC)?1.f:0.f);
    P2[1] = pk2((c0+2==SOSC)?1.f:0.f, (c0+3==SOSC)?1.f:0.f);
    int eC = 0;                       // exact integer log2 offset

    const float* fbase = feats + (size_t)bb * NCLS + c0;
    const float* mbase = mask + bb;
    const unsigned fstep = (unsigned)batch * NCLS;
    const unsigned mstep = (unsigned)batch;

    // 8-deep prefetch of exp(feat) (4 classes/lane) and mask scalar.
    u64 fe[8][2]; float mk[8];
#pragma unroll
    for (int j = 0; j < 8; ++j){
        int tc = (j < seq) ? j : (seq - 1);
        float4 f4 = *reinterpret_cast<const float4*>(fbase + (size_t)((unsigned)tc * fstep));
        fe[j][0] = pk2(ex2f(f4.x*LOG2E), ex2f(f4.y*LOG2E));
        fe[j][1] = pk2(ex2f(f4.z*LOG2E), ex2f(f4.w*LOG2E));
        mk[j] = mbase[(unsigned)tc * mstep];
    }

    int t0 = 0;
    for (; t0 + 8 <= seq; t0 += 8){
#pragma unroll
        for (int j = 0; j < 8; ++j){
            const bool pm = (mk[j] != 0.0f);   // binary-mask predicate, off-path
            // rescale folded into fe[j], BEFORE exchange (fully off-path).
            // Gated on mask!=0 so kept state never desyncs from eC.
            if ((j & 3) == 0){
                float plo, phi; up2(P2[0], plo, phi);
                float piv = __shfl_sync(0xffffffffu, plo, lane & 16);
                float r = 1.0f;
                if (pm) r = po2_rescale(piv, eC);
                u64 rr = pk2(r, r);
                fe[j][0] = fmul2(fe[j][0], rr);   // exact: r is power of 2
                fe[j][1] = fmul2(fe[j][1], rr);
            }
            // all-register exchange: gather this lane's 16 k-values (8 u64)
            u64 q[8];
#pragma unroll
            for (int qi = 0; qi < 4; ++qi){
                q[2*qi]   = shfl64(P2[0], xbase + qi);
                q[2*qi+1] = shfl64(P2[1], xbase + qi);
            }
            float s[4];
#pragma unroll
            for (int ci = 0; ci < 4; ++ci){
                u64 aA = 0ull, aB = 0ull;
                aA = ffma2(E2[ci][0], q[0], aA);
                aB = ffma2(E2[ci][1], q[1], aB);
                aA = ffma2(E2[ci][2], q[2], aA);
                aB = ffma2(E2[ci][3], q[3], aB);
                aA = ffma2(E2[ci][4], q[4], aA);
                aB = ffma2(E2[ci][5], q[5], aB);
                aA = ffma2(E2[ci][6], q[6], aA);
                aB = ffma2(E2[ci][7], q[7], aB);
                u64 a = fadd2(aA, aB);
                float lo, hi; up2(a, lo, hi);
                s[ci] = lo + hi;                       // partial over this k-half
            }
            // combine with k-partner (lane ^ 8): full 32-k dot
#pragma unroll
            for (int ci = 0; ci < 4; ++ci)
                s[ci] += __shfl_xor_sync(0xffffffffu, s[ci], 8);
            u64 Pn0 = fmul2(pk2(s[0], s[1]), fe[j][0]);
            u64 Pn1 = fmul2(pk2(s[2], s[3]), fe[j][1]);
            // SEL blend: rounding-free, exact for binary masks, any scale mix
            P2[0] = pm ? Pn0 : P2[0];
            P2[1] = pm ? Pn1 : P2[1];
            // prefetch step t0+8+j (index clamped BEFORE offset computation)
            {
                int tn = t0 + 8 + j;
                int tc = (tn < seq) ? tn : (seq - 1);
                float4 f4 = *reinterpret_cast<const float4*>(fbase + (size_t)((unsigned)tc * fstep));
                fe[j][0] = pk2(ex2f(f4.x*LOG2E), ex2f(f4.y*LOG2E));
                fe[j][1] = pk2(ex2f(f4.z*LOG2E), ex2f(f4.w*LOG2E));
                mk[j] = mbase[(unsigned)tc * mstep];
            }
        }
    }
    // tail (seq % 8 != 0; not hit for seq=512)
    for (int t = t0; t < seq; ++t){
        float4 f4 = *reinterpret_cast<const float4*>(fbase + (size_t)((unsigned)t * fstep));
        u64 fe0 = pk2(ex2f(f4.x*LOG2E), ex2f(f4.y*LOG2E));
        u64 fe1 = pk2(ex2f(f4.z*LOG2E), ex2f(f4.w*LOG2E));
        float m = mbase[(unsigned)t * mstep];
        const bool pm = (m != 0.0f);
        {   // fe-folded rescale, every tail step
            float plo, phi; up2(P2[0], plo, phi);
            float piv = __shfl_sync(0xffffffffu, plo, lane & 16);
            float r = 1.0f;
            if (pm) r = po2_rescale(piv, eC);
            u64 rr = pk2(r, r);
            fe0 = fmul2(fe0, rr);
            fe1 = fmul2(fe1, rr);
        }
        u64 q[8];
#pragma unroll
        for (int qi = 0; qi < 4; ++qi){
            q[2*qi]   = shfl64(P2[0], xbase + qi);
            q[2*qi+1] = shfl64(P2[1], xbase + qi);
        }
        float s[4];
#pragma unroll
        for (int ci = 0; ci < 4; ++ci){
            u64 aA = 0ull, aB = 0ull;
#pragma unroll
            for (int kp = 0; kp < 8; kp += 2){
                aA = ffma2(E2[ci][kp],   q[kp],   aA);
                aB = ffma2(E2[ci][kp+1], q[kp+1], aB);
            }
            u64 a = fadd2(aA, aB);
            float lo, hi; up2(a, lo, hi);
            s[ci] = lo + hi;
        }
#pragma unroll
        for (int ci = 0; ci < 4; ++ci)
            s[ci] += __shfl_xor_sync(0xffffffffu, s[ci], 8);
        u64 Pn0 = fmul2(pk2(s[0], s[1]), fe0);
        u64 Pn1 = fmul2(pk2(s[2], s[3]), fe1);
        P2[0] = pm ? Pn0 : P2[0];
        P2[1] = pm ? Pn1 : P2[1];
    }

    // Epilogue: out[b] = ln2 * (eC + log2( sum_c P[c] * exp(T[EOS,c]) ))
    u64 w2 = fmul2(P2[0], ee2[0]);
    w2 = ffma2(P2[1], ee2[1], w2);
    float lo, hi; up2(w2, lo, hi);
    float v = lo + hi;                 // sum over this lane's 4 classes
    // reduce over the 8 class groups (values identical across k-partners)
    v += __shfl_xor_sync(0xffffffffu, v, 1);
    v += __shfl_xor_sync(0xffffffffu, v, 2);
    v += __shfl_xor_sync(0xffffffffu, v, 4);
    if (g == 0 && real)
        out[bb] = ((float)eC + lg2f_(v)) * LN2F;
}

extern "C" void kernel_launch(void* const* d_in, const int* in_sizes, int n_in,
                              void* d_out, int out_size)
{
    const float* feats = (const float*)d_in[0];
    const float* mask  = (const float*)d_in[1];
    const float* trans = (const float*)d_in[2];
    float* out = (float*)d_out;

    const int batch = out_size;                 // out is (batch,)
    const int seq   = in_sizes[1] / batch;      // mask is (seq, batch)

    const int blocks = (batch + 1) / 2;         // 1 warp = 2 batches
    crf_fwd<<<blocks, 32>>>(feats, mask, trans, out, seq, batch);
}